// round 3
// baseline (speedup 1.0000x reference)
#include <cuda_runtime.h>
#include <math.h>

#define BB 64
#define TT 2048
#define HH 256
#define CH 128
#define NCHUNK 16              // TT / CH
#define NBLK (BB * NCHUNK)     // 1024
#define NTHR 128               // 128 threads = 128 channel-pairs
#define FAN_EPS 1e-4f
#define ISD_MAX 1e4f           // 1/FAN_EPS

// Transposed partial layout: [slice][h][blk] -> coalesced reduction reads.
__device__ float g_psum[2][HH][NBLK];
__device__ float g_psumsq[2][HH][NBLK];
__device__ float g_cA[2][HH];   // gamma/sd per slice
__device__ float g_cB[2][HH];   // beta - mu*gamma/sd per slice

// ---------- packed f32x2 helpers (sm_103a) ----------
typedef unsigned long long f2;

__device__ __forceinline__ f2 pk2(float lo, float hi) {
    f2 r; asm("mov.b64 %0, {%1, %2};" : "=l"(r) : "f"(lo), "f"(hi)); return r;
}
__device__ __forceinline__ void up2(f2 v, float& lo, float& hi) {
    asm("mov.b64 {%0, %1}, %2;" : "=f"(lo), "=f"(hi) : "l"(v));
}
__device__ __forceinline__ f2 add2(f2 a, f2 b) {
    f2 r; asm("add.rn.f32x2 %0, %1, %2;" : "=l"(r) : "l"(a), "l"(b)); return r;
}
__device__ __forceinline__ f2 mul2(f2 a, f2 b) {
    f2 r; asm("mul.rn.f32x2 %0, %1, %2;" : "=l"(r) : "l"(a), "l"(b)); return r;
}
__device__ __forceinline__ f2 fma2(f2 a, f2 b, f2 c) {
    f2 r; asm("fma.rn.f32x2 %0, %1, %2, %3;" : "=l"(r) : "l"(a), "l"(b), "l"(c)); return r;
}

// Packed window stats: mu (packed) and clamped inverse-sd (packed).
// No fmax(var,0) needed: var<0 -> rsqrt=NaN -> fminf(NaN,1e4)=1e4, which is
// exactly the clamp result (FMA exact cancellation yields +0, never -0).
__device__ __forceinline__ void wstat2(f2 s1, f2 s2, f2 invw, f2 invwm1, f2 NEG1,
                                       f2& mu, f2& isd) {
    mu = mul2(s1, invw);
    f2 ns1 = mul2(s1, NEG1);
    f2 var = mul2(fma2(ns1, mu, s2), invwm1);
    float vl, vh; up2(var, vl, vh);
    float il = fminf(rsqrtf(vl), ISD_MAX);
    float ih = fminf(rsqrtf(vh), ISD_MAX);
    isd = pk2(il, ih);
}

template <bool WRITE, bool EDGE>
__device__ __forceinline__ void process_chunk(
    const f2* __restrict__ px2, f2* __restrict__ po2, int t0,
    f2 al5, f2 al10, f2 al20, f2 cA, f2 cB, f2& accS, f2& accQ)
{
    const f2 NEG1  = pk2(-1.0f, -1.0f);
    const f2 IW5   = pk2(0.2f, 0.2f),   IM5  = pk2(0.25f, 0.25f);
    const f2 IW10  = pk2(0.1f, 0.1f),   IM10 = pk2(1.0f/9.0f, 1.0f/9.0f);
    const f2 IW20  = pk2(0.05f, 0.05f), IM20 = pk2(1.0f/19.0f, 1.0f/19.0f);

    f2 s1_5 = 0, s2_5 = 0, s1_10 = 0, s2_10 = 0, s1_20 = 0, s2_20 = 0;
    f2 fmu5 = 0, fis5 = 0, fmu10 = 0, fis10 = 0, fmu20 = 0, fis20 = 0;

    if (EDGE) {
        // first-full-window stats (edge padding) from x[0..19]
        f2 s1 = 0, s2 = 0;
#pragma unroll
        for (int j = 0; j < 20; j++) {
            f2 v = px2[j * (HH / 2)];
            s1 = add2(s1, v);
            s2 = fma2(v, v, s2);
            if (j == 4)  wstat2(s1, s2, IW5,  IM5,  NEG1, fmu5,  fis5);
            if (j == 9)  wstat2(s1, s2, IW10, IM10, NEG1, fmu10, fis10);
            if (j == 19) wstat2(s1, s2, IW20, IM20, NEG1, fmu20, fis20);
        }
    } else {
        // warm-up sums from the halo x[t0-20 .. t0-1]
#pragma unroll
        for (int j = 0; j < 20; j++) {
            f2 v = px2[(t0 - 20 + j) * (HH / 2)];
            s1_20 = add2(s1_20, v); s2_20 = fma2(v, v, s2_20);
            if (j >= 10) { s1_10 = add2(s1_10, v); s2_10 = fma2(v, v, s2_10); }
            if (j >= 15) { s1_5  = add2(s1_5,  v); s2_5  = fma2(v, v, s2_5);  }
        }
    }

#pragma unroll 4
    for (int t = t0; t < t0 + CH; ++t) {
        f2 xt  = px2[t * (HH / 2)];
        f2 x5, x10, x20;
        if (EDGE) {
            x5  = (t >= 5)  ? px2[(t - 5)  * (HH / 2)] : 0ULL;
            x10 = (t >= 10) ? px2[(t - 10) * (HH / 2)] : 0ULL;
            x20 = (t >= 20) ? px2[(t - 20) * (HH / 2)] : 0ULL;
        } else {
            x5  = px2[(t - 5)  * (HH / 2)];
            x10 = px2[(t - 10) * (HH / 2)];
            x20 = px2[(t - 20) * (HH / 2)];
        }
        // s1 += (xt - xw);  s2 += (xt - xw)*(xt + xw)   [= xt^2 - xw^2]
        {
            f2 d = fma2(x5, NEG1, xt);  f2 p = add2(xt, x5);
            s1_5 = add2(s1_5, d);       s2_5 = fma2(d, p, s2_5);
        }
        {
            f2 d = fma2(x10, NEG1, xt); f2 p = add2(xt, x10);
            s1_10 = add2(s1_10, d);     s2_10 = fma2(d, p, s2_10);
        }
        {
            f2 d = fma2(x20, NEG1, xt); f2 p = add2(xt, x20);
            s1_20 = add2(s1_20, d);     s2_20 = fma2(d, p, s2_20);
        }

        f2 mu5, is5, mu10, is10, mu20, is20;
        wstat2(s1_5,  s2_5,  IW5,  IM5,  NEG1, mu5,  is5);
        wstat2(s1_10, s2_10, IW10, IM10, NEG1, mu10, is10);
        wstat2(s1_20, s2_20, IW20, IM20, NEG1, mu20, is20);

        if (EDGE) {
            if (t < 4)  { mu5  = fmu5;  is5  = fis5;  }
            if (t < 9)  { mu10 = fmu10; is10 = fis10; }
            if (t < 19) { mu20 = fmu20; is20 = fis20; }
        }

        // f = xt*(w5+w10+w20) - (mu5*w5 + mu10*w10 + mu20*w20),  w = isd*alpha
        f2 w5  = mul2(is5,  al5);
        f2 w10 = mul2(is10, al10);
        f2 w20 = mul2(is20, al20);
        f2 wsum = add2(add2(w5, w10), w20);
        f2 msum = fma2(mu20, w20, fma2(mu10, w10, mul2(mu5, w5)));
        f2 f = fma2(msum, NEG1, mul2(xt, wsum));

        if (WRITE) {
            po2[t * (HH / 2)] = add2(fma2(f, cA, xt), cB);
        } else {
            accS = add2(accS, f);
            accQ = fma2(f, f, accQ);
        }
    }
}

template <bool WRITE>
__global__ __launch_bounds__(NTHR, 6)
void fan_kernel(const float* __restrict__ x, const float* __restrict__ alpha,
                float* __restrict__ out) {
    const int c  = blockIdx.x & (NCHUNK - 1);
    const int b  = blockIdx.x >> 4;
    const int tid = threadIdx.x;
    const int h0 = 2 * tid;
    const int t0 = c * CH;

    const f2* px2 = (const f2*)(x + ((size_t)b * TT) * HH) + tid;
    f2* po2 = (f2*)(out + ((size_t)b * TT) * HH) + tid;

    // softmax over the 3 window weights, per channel, packed per pair
    f2 al5, al10, al20;
    {
        float w[2][3];
#pragma unroll
        for (int ch = 0; ch < 2; ++ch) {
            float a0 = alpha[(h0 + ch) * 3 + 0];
            float a1 = alpha[(h0 + ch) * 3 + 1];
            float a2 = alpha[(h0 + ch) * 3 + 2];
            float mx = fmaxf(a0, fmaxf(a1, a2));
            float e0 = expf(a0 - mx), e1 = expf(a1 - mx), e2 = expf(a2 - mx);
            float inv = 1.0f / (e0 + e1 + e2);
            w[ch][0] = e0 * inv; w[ch][1] = e1 * inv; w[ch][2] = e2 * inv;
        }
        al5  = pk2(w[0][0], w[1][0]);
        al10 = pk2(w[0][1], w[1][1]);
        al20 = pk2(w[0][2], w[1][2]);
    }

    // SAN affine coefficients — uniform per chunk (slice boundaries 1024/1536
    // are multiples of CH).
    f2 cA = 0, cB = 0;
    if (WRITE) {
        const float inv1 = 1.0f / (1.0f + FAN_EPS);
        const float inv2 = 1.0f / (2.0f + FAN_EPS);
        float a[2], bb[2];
#pragma unroll
        for (int ch = 0; ch < 2; ++ch) {
            float A0 = g_cA[0][h0 + ch], B0 = g_cB[0][h0 + ch];
            float A1 = g_cA[1][h0 + ch], B1 = g_cB[1][h0 + ch];
            if (c < 8)       { a[ch] = A0 * inv1;        bb[ch] = B0 * inv1; }
            else if (c < 12) { a[ch] = (A0 + A1) * inv2; bb[ch] = (B0 + B1) * inv2; }
            else             { a[ch] = A1 * inv1;        bb[ch] = B1 * inv1; }
        }
        cA = pk2(a[0], a[1]);
        cB = pk2(bb[0], bb[1]);
    }

    f2 accS = 0, accQ = 0;
    if (c == 0)
        process_chunk<WRITE, true >(px2, po2, t0, al5, al10, al20, cA, cB, accS, accQ);
    else
        process_chunk<WRITE, false>(px2, po2, t0, al5, al10, al20, cA, cB, accS, accQ);

    if (!WRITE) {
        const int blk = blockIdx.x;
        const bool in0 = (c < 12);   // t < 1536
        const bool in1 = (c >= 8);   // t >= 1024
        float sl, sh, ql, qh;
        up2(accS, sl, sh); up2(accQ, ql, qh);
        g_psum[0][h0][blk]       = in0 ? sl : 0.0f;
        g_psum[0][h0 + 1][blk]   = in0 ? sh : 0.0f;
        g_psumsq[0][h0][blk]     = in0 ? ql : 0.0f;
        g_psumsq[0][h0 + 1][blk] = in0 ? qh : 0.0f;
        g_psum[1][h0][blk]       = in1 ? sl : 0.0f;
        g_psum[1][h0 + 1][blk]   = in1 ? sh : 0.0f;
        g_psumsq[1][h0][blk]     = in1 ? ql : 0.0f;
        g_psumsq[1][h0 + 1][blk] = in1 ? qh : 0.0f;
    }
}

// One block per (slice, h): 256 threads tree-reduce the 1024 partials.
__global__ __launch_bounds__(256)
void stats_kernel(const float* __restrict__ gamma, const float* __restrict__ beta) {
    const int s = blockIdx.x >> 8;
    const int h = blockIdx.x & (HH - 1);
    const int tid = threadIdx.x;

    double dS = 0.0, dQ = 0.0;
#pragma unroll
    for (int i = 0; i < NBLK / 256; ++i) {
        dS += (double)g_psum[s][h][tid + i * 256];
        dQ += (double)g_psumsq[s][h][tid + i * 256];
    }
    __shared__ double shS[256], shQ[256];
    shS[tid] = dS; shQ[tid] = dQ;
    __syncthreads();
    for (int off = 128; off > 0; off >>= 1) {
        if (tid < off) { shS[tid] += shS[tid + off]; shQ[tid] += shQ[tid + off]; }
        __syncthreads();
    }
    if (tid == 0) {
        double S = shS[0], Q = shQ[0];
        const double n = (s == 0) ? (double)BB * 1536.0 : (double)BB * 1024.0;
        double mu  = S / n;
        double var = (Q - S * S / n) / (n - 1.0);
        if (var < 0.0) var = 0.0;
        double sd = sqrt(var);
        if (sd < 1e-4) sd = 1e-4;
        float g  = gamma[s * HH + h];
        float be = beta[s * HH + h];
        float a  = (float)((double)g / sd);
        g_cA[s][h] = a;
        g_cB[s][h] = be - (float)mu * a;
    }
}

extern "C" void kernel_launch(void* const* d_in, const int* in_sizes, int n_in,
                              void* d_out, int out_size) {
    (void)in_sizes; (void)n_in; (void)out_size;
    const float* x     = (const float*)d_in[0];
    const float* alpha = (const float*)d_in[1];
    const float* gamma = (const float*)d_in[2];
    const float* beta  = (const float*)d_in[3];
    float* out = (float*)d_out;

    fan_kernel<false><<<NBLK, NTHR>>>(x, alpha, nullptr);
    stats_kernel<<<2 * HH, 256>>>(gamma, beta);
    fan_kernel<true><<<NBLK, NTHR>>>(x, alpha, out);
}